// round 9
// baseline (speedup 1.0000x reference)
#include <cuda_runtime.h>
#include <cstdint>

// UpSmpl — conv3d(64->256,3x3x3,pad1) + pixel-shuffle x2 + skip,
// via warp-level mma.sync m16n8k8 tf32 + ldmatrix fragment loads.
// x: (1,64,17,128,128) f32   W: (256,64,3,3,3) f32   b: (256,) f32
// out: (1,32,33,256,256) f32

#define ZP 19
#define YP 130
#define XPD 130
#define ICN 64
#define NTAP 27
#define NOC 256

__device__ __align__(256) float g_xT[(size_t)ZP * YP * XPD * ICN]; // padded, tf32-rounded, [z][y][x][ic]
__device__ __align__(256) float g_Wt[(size_t)NTAP * NOC * ICN];    // tf32-rounded, [tap][oc][ic]

#define APITCH 36
#define BPITCH 36
#define ABUF (130 * APITCH)    // 4680 floats
#define BBUF (128 * BPITCH)    // 4608 floats
#define SMEM_FLOATS (3 * ABUF + 3 * BBUF)
#define SMEM_BYTES  (SMEM_FLOATS * 4)

// ---------------- PTX helpers ----------------
__device__ __forceinline__ uint32_t smem_u32(const void* p) {
    uint32_t a;
    asm("{ .reg .u64 t; cvta.to.shared.u64 t, %1; cvt.u32.u64 %0, t; }" : "=r"(a) : "l"(p));
    return a;
}
__device__ __forceinline__ uint32_t rna_tf32(float v) {
    uint32_t r; asm("cvt.rna.tf32.f32 %0, %1;" : "=r"(r) : "f"(v)); return r;
}
__device__ __forceinline__ void cpa16(uint32_t dst, const void* src) {
    asm volatile("cp.async.cg.shared.global [%0], [%1], 16;" :: "r"(dst), "l"(src));
}
#define CP_COMMIT() asm volatile("cp.async.commit_group;")
#define CP_WAIT1()  asm volatile("cp.async.wait_group 1;" ::: "memory")

__device__ __forceinline__ void mma8(float* d, const uint32_t* a, const uint32_t* b) {
    asm volatile(
        "mma.sync.aligned.m16n8k8.row.col.f32.tf32.tf32.f32 "
        "{%0,%1,%2,%3}, {%4,%5,%6,%7}, {%8,%9}, {%0,%1,%2,%3};"
        : "+f"(d[0]), "+f"(d[1]), "+f"(d[2]), "+f"(d[3])
        : "r"(a[0]), "r"(a[1]), "r"(a[2]), "r"(a[3]), "r"(b[0]), "r"(b[1]));
}
__device__ __forceinline__ void ldsm4(uint32_t& r0, uint32_t& r1, uint32_t& r2,
                                      uint32_t& r3, uint32_t addr) {
    asm volatile("ldmatrix.sync.aligned.m8n8.x4.shared.b16 {%0,%1,%2,%3}, [%4];"
                 : "=r"(r0), "=r"(r1), "=r"(r2), "=r"(r3) : "r"(addr));
}

// ---------------- prep kernels ----------------
__global__ void zero_xT_kernel() {
    size_t i = (size_t)blockIdx.x * blockDim.x + threadIdx.x;
    size_t n4 = (size_t)ZP * YP * XPD * ICN / 4;
    if (i < n4) ((float4*)g_xT)[i] = make_float4(0.f, 0.f, 0.f, 0.f);
}

__global__ void prep_x_kernel(const float* __restrict__ xin) {
    __shared__ float ts[64 * 129];
    const int tid = threadIdx.x;
    const int z = blockIdx.y, y = blockIdx.x;
    for (int i = tid; i < 2048; i += 256) {          // 64 ic x 32 float4
        int ic = i >> 5, xq = i & 31;
        float4 v = ((const float4*)xin)[(((size_t)ic * 17 + z) * 128 + y) * 32 + xq];
        ts[ic * 129 + xq * 4 + 0] = __uint_as_float(rna_tf32(v.x));
        ts[ic * 129 + xq * 4 + 1] = __uint_as_float(rna_tf32(v.y));
        ts[ic * 129 + xq * 4 + 2] = __uint_as_float(rna_tf32(v.z));
        ts[ic * 129 + xq * 4 + 3] = __uint_as_float(rna_tf32(v.w));
    }
    __syncthreads();
    size_t obase = (((size_t)(z + 1) * YP + (y + 1)) * XPD + 1) * ICN;
    for (int i = tid; i < 2048; i += 256) {          // 128 x  x 16 ic-quads
        int xx = i >> 4, icq = i & 15;
        float4 w = make_float4(ts[(icq * 4 + 0) * 129 + xx], ts[(icq * 4 + 1) * 129 + xx],
                               ts[(icq * 4 + 2) * 129 + xx], ts[(icq * 4 + 3) * 129 + xx]);
        ((float4*)(g_xT + obase + (size_t)xx * ICN))[icq] = w;
    }
}

__global__ void prep_w_kernel(const float* __restrict__ win) {
    const int oc = blockIdx.x;
    for (int i = threadIdx.x; i < 64 * 27; i += 256) {
        int ic = i / 27, tap = i % 27;
        g_Wt[((size_t)tap * NOC + oc) * ICN + ic] =
            __uint_as_float(rna_tf32(win[(size_t)oc * 1728 + i]));
    }
}

// ---------------- main MMA kernel ----------------
// CTA: M=128 pixels (one (z,y) row), N=128 oc (half), 256 thr = 8 warps (4M x 2N).
// 54 K-stages = 18 A-slabs (kz,ky,half) x 3 kx (A slab reused via row shift).
__global__ void __launch_bounds__(256, 2)
upsmpl_mma_kernel(const float* __restrict__ xin, const float* __restrict__ bin,
                  float* __restrict__ outp)
{
    extern __shared__ float sm[];
    const int tid  = threadIdx.x;
    const int lane = tid & 31, wid = tid >> 5;
    const int g = lane >> 2, tig = lane & 3;
    const int wm = wid & 3, wn = wid >> 2;

    const int y  = blockIdx.x;          // 0..127
    const int z  = blockIdx.y;          // 0..16
    const int ocbase = blockIdx.z * 128;

    const uint32_t sA = smem_u32(sm);
    const uint32_t sB = sA + 3u * ABUF * 4u;

    // ldmatrix per-lane address pieces: matrix m = lane/8.
    // m0: rows 0-7 col-lo, m1: rows 8-15 col-lo, m2: rows 0-7 col-hi, m3: rows 8-15 col-hi
    const int lrow  = ((lane >> 3) & 1) * 8 + (lane & 7);
    const int lcol4 = (lane >> 4) * 16;                 // +4 floats for col-hi
    const uint32_t aLaneOff = (uint32_t)((wm * 32 + lrow) * APITCH * 4 + lcol4);
    const uint32_t bLaneOff = (uint32_t)((wn * 64 + lrow) * BPITCH * 4 + lcol4);

    auto loadA = [&](int s) {           // slab s = (kz*3+ky)*2 + half
        const int kz = s / 6, ky = (s / 2) % 3, half = s & 1;
        const float* src = g_xT + ((size_t)(z + kz) * YP + (y + ky)) * XPD * ICN + half * 32;
        const uint32_t dst = sA + (uint32_t)(s % 3) * ABUF * 4u;
        for (int i = tid; i < 1040; i += 256) {     // 130 rows x 8 x 16B
            int r = i >> 3, c = i & 7;
            cpa16(dst + (uint32_t)(r * APITCH * 4 + c * 16),
                  (const char*)(src + (size_t)r * ICN) + c * 16);
        }
    };
    auto loadB = [&](int j) {           // stage j: slab j/3, kx j%3
        const int s = j / 3, kx = j % 3;
        const int kz = s / 6, ky = (s / 2) % 3, half = s & 1;
        const int tap = (kz * 3 + ky) * 3 + kx;
        const float* src = g_Wt + ((size_t)tap * NOC + ocbase) * ICN + half * 32;
        const uint32_t dst = sB + (uint32_t)(j % 3) * BBUF * 4u;
        for (int i = tid; i < 1024; i += 256) {     // 128 rows x 8 x 16B
            int r = i >> 3, c = i & 7;
            cpa16(dst + (uint32_t)(r * BPITCH * 4 + c * 16),
                  (const char*)(src + (size_t)r * ICN) + c * 16);
        }
    };

    float d[2][8][4];
    #pragma unroll
    for (int mf = 0; mf < 2; ++mf)
        #pragma unroll
        for (int f = 0; f < 8; ++f)
            #pragma unroll
            for (int r = 0; r < 4; ++r) d[mf][f][r] = 0.f;

    loadA(0); loadB(0); CP_COMMIT();
    loadA(1); loadB(1); CP_COMMIT();

    for (int j = 0; j < 54; ++j) {
        CP_WAIT1();
        __syncthreads();   // publishes stage-j data; also fences stage j-1 reads
                           // so overwriting buffer (j+2)%3 below is safe.

        const uint32_t Ab = sA + (uint32_t)((j / 3) % 3) * ABUF * 4u;
        const uint32_t Bb = sB + (uint32_t)(j % 3) * BBUF * 4u;
        const int kx = j - (j / 3) * 3;
        const uint32_t aBase = Ab + aLaneOff + (uint32_t)(kx * APITCH * 4);
        const uint32_t bBase = Bb + bLaneOff;

        #pragma unroll
        for (int c = 0; c < 4; ++c) {
            uint32_t a[2][4], b[8][2];
            #pragma unroll
            for (int mf = 0; mf < 2; ++mf)
                ldsm4(a[mf][0], a[mf][1], a[mf][2], a[mf][3],
                      aBase + (uint32_t)(mf * 16 * APITCH * 4 + c * 32));
            #pragma unroll
            for (int f2 = 0; f2 < 4; ++f2)
                ldsm4(b[2 * f2][0], b[2 * f2 + 1][0], b[2 * f2][1], b[2 * f2 + 1][1],
                      bBase + (uint32_t)(f2 * 16 * BPITCH * 4 + c * 32));
            #pragma unroll
            for (int mf = 0; mf < 2; ++mf)
                #pragma unroll
                for (int f = 0; f < 8; ++f)
                    mma8(d[mf][f], a[mf], b[f]);
        }

        if (j + 2 < 54) loadB(j + 2);
        if ((j + 2) % 3 == 1) {          // A slab s2 committed in group 3*s2-2
            int s2 = (j + 4) / 3;
            if (s2 < 18) loadA(s2);
        }
        CP_COMMIT();                     // one group per iteration (may be empty)
    }

    // ---------------- epilogue: bias + shuffle scatter + skip ----------------
    #pragma unroll
    for (int mf = 0; mf < 2; ++mf) {
        #pragma unroll
        for (int rh = 0; rh < 2; ++rh) {
            const int x = wm * 32 + mf * 16 + rh * 8 + g;
            if (z == 0) {
                #pragma unroll
                for (int f = 0; f < 4; ++f) {       // f>=4 -> oc&32 -> discarded
                    #pragma unroll
                    for (int par = 0; par < 2; ++par) {
                        const int oc = ocbase + wn * 64 + f * 8 + 2 * tig + par;
                        const int q = (oc >> 6) & 1, p = oc >> 7, nn = oc & 31;
                        const int sic = (p * 64 + q * 32 + nn) >> 1;
                        const float v = d[mf][f][rh * 2 + par] + bin[oc]
                                      + xin[(size_t)sic * 17 * 16384 + (size_t)y * 128 + x];
                        outp[((size_t)nn * 33 * 256 + (2 * y + p)) * 256 + 2 * x + q] = v;
                    }
                }
            } else {
                #pragma unroll
                for (int f = 0; f < 4; ++f) {
                    #pragma unroll
                    for (int par = 0; par < 2; ++par) {
                        const int oc0 = ocbase + wn * 64 + f * 8 + 2 * tig + par;
                        const int oc1 = oc0 + 32;   // q=1 partner
                        const float v0 = d[mf][f][rh * 2 + par] + bin[oc0]
                            + xin[((size_t)(oc0 >> 2) * 17 + z) * 16384 + (size_t)y * 128 + x];
                        const float v1 = d[mf][f + 4][rh * 2 + par] + bin[oc1]
                            + xin[((size_t)(oc1 >> 2) * 17 + z) * 16384 + (size_t)y * 128 + x];
                        const int nn = oc0 & 31, p = (oc0 >> 6) & 1, a = oc0 >> 7;
                        const size_t o = (((size_t)nn * 33 + (2 * z - 1 + a)) * 256
                                          + (2 * y + p)) * 256 + 2 * x;
                        *(float2*)(outp + o) = make_float2(v0, v1);
                    }
                }
            }
        }
    }
}

extern "C" void kernel_launch(void* const* d_in, const int* in_sizes, int n_in,
                              void* d_out, int out_size) {
    const float* x = (const float*)d_in[0];
    const float* W = (const float*)d_in[1];
    const float* b = (const float*)d_in[2];
    float* out = (float*)d_out;

    cudaFuncSetAttribute(upsmpl_mma_kernel,
                         cudaFuncAttributeMaxDynamicSharedMemorySize, SMEM_BYTES);

    size_t n4 = (size_t)ZP * YP * XPD * ICN / 4;
    zero_xT_kernel<<<(unsigned)((n4 + 255) / 256), 256>>>();
    prep_x_kernel<<<dim3(128, 17), 256>>>(x);
    prep_w_kernel<<<256, 256>>>(W);
    upsmpl_mma_kernel<<<dim3(128, 17, 2), 256, SMEM_BYTES>>>(x, b, out);
}

// round 10
// speedup vs baseline: 1.9652x; 1.9652x over previous
#include <cuda_runtime.h>
#include <cuda_fp16.h>
#include <cstdint>

// UpSmpl — conv3d(64->256,3x3x3,pad1) + pixel-shuffle x2 + skip,
// via warp-level mma.sync m16n8k16 fp16 (f32 accum) + ldmatrix.
// x: (1,64,17,128,128) f32   W: (256,64,3,3,3) f32   b: (256,) f32
// out: (1,32,33,256,256) f32

#define ZP 19
#define YP 130
#define XPD 130
#define ICN 64
#define NTAP 27
#define NOC 256

__device__ __align__(256) __half g_xTh[(size_t)ZP * YP * XPD * ICN]; // padded, [z][y][x][ic]
__device__ __align__(256) __half g_Wth[(size_t)NTAP * NOC * ICN];    // [tap][oc][ic]

#define APITCH 72              // halves per row (144 B)
#define BPITCH 72
#define ABUF (130 * APITCH)    // halves
#define BBUF (128 * BPITCH)
#define SMEM_BYTES ((3 * ABUF + 3 * BBUF) * 2)

// ---------------- PTX helpers ----------------
__device__ __forceinline__ uint32_t smem_u32(const void* p) {
    uint32_t a;
    asm("{ .reg .u64 t; cvta.to.shared.u64 t, %1; cvt.u32.u64 %0, t; }" : "=r"(a) : "l"(p));
    return a;
}
__device__ __forceinline__ void cpa16(uint32_t dst, const void* src) {
    asm volatile("cp.async.cg.shared.global [%0], [%1], 16;" :: "r"(dst), "l"(src));
}
#define CP_COMMIT() asm volatile("cp.async.commit_group;")
#define CP_WAIT1()  asm volatile("cp.async.wait_group 1;" ::: "memory")

__device__ __forceinline__ void mma16(float* d, const uint32_t* a, const uint32_t* b) {
    asm volatile(
        "mma.sync.aligned.m16n8k16.row.col.f32.f16.f16.f32 "
        "{%0,%1,%2,%3}, {%4,%5,%6,%7}, {%8,%9}, {%0,%1,%2,%3};"
        : "+f"(d[0]), "+f"(d[1]), "+f"(d[2]), "+f"(d[3])
        : "r"(a[0]), "r"(a[1]), "r"(a[2]), "r"(a[3]), "r"(b[0]), "r"(b[1]));
}
__device__ __forceinline__ void ldsm4(uint32_t& r0, uint32_t& r1, uint32_t& r2,
                                      uint32_t& r3, uint32_t addr) {
    asm volatile("ldmatrix.sync.aligned.m8n8.x4.shared.b16 {%0,%1,%2,%3}, [%4];"
                 : "=r"(r0), "=r"(r1), "=r"(r2), "=r"(r3) : "r"(addr));
}

// ---------------- prep kernels ----------------
__global__ void zero_xT_kernel() {
    size_t i = (size_t)blockIdx.x * blockDim.x + threadIdx.x;
    size_t n8 = (size_t)ZP * YP * XPD * ICN / 8;     // uint4 = 8 halves
    if (i < n8) ((uint4*)g_xTh)[i] = make_uint4(0, 0, 0, 0);
}

__global__ void prep_x_kernel(const float* __restrict__ xin) {
    __shared__ unsigned short ts[64 * 129];
    const int tid = threadIdx.x;
    const int z = blockIdx.y, y = blockIdx.x;
    for (int i = tid; i < 2048; i += 256) {          // 64 ic x 32 float4
        int ic = i >> 5, xq = i & 31;
        float4 v = ((const float4*)xin)[(((size_t)ic * 17 + z) * 128 + y) * 32 + xq];
        ts[ic * 129 + xq * 4 + 0] = __half_as_ushort(__float2half_rn(v.x));
        ts[ic * 129 + xq * 4 + 1] = __half_as_ushort(__float2half_rn(v.y));
        ts[ic * 129 + xq * 4 + 2] = __half_as_ushort(__float2half_rn(v.z));
        ts[ic * 129 + xq * 4 + 3] = __half_as_ushort(__float2half_rn(v.w));
    }
    __syncthreads();
    size_t obase = (((size_t)(z + 1) * YP + (y + 1)) * XPD + 1) * ICN;
    for (int i = tid; i < 2048; i += 256) {          // 128 x  x 16 ic-quads
        int xx = i >> 4, icq = i & 15;
        uint2 w;
        w.x = (uint32_t)ts[(icq * 4 + 0) * 129 + xx]
            | ((uint32_t)ts[(icq * 4 + 1) * 129 + xx] << 16);
        w.y = (uint32_t)ts[(icq * 4 + 2) * 129 + xx]
            | ((uint32_t)ts[(icq * 4 + 3) * 129 + xx] << 16);
        *(uint2*)(g_xTh + obase + (size_t)xx * ICN + icq * 4) = w;
    }
}

__global__ void prep_w_kernel(const float* __restrict__ win) {
    const int oc = blockIdx.x;
    for (int i = threadIdx.x; i < 64 * 27; i += 256) {
        int ic = i / 27, tap = i % 27;
        g_Wth[((size_t)tap * NOC + oc) * ICN + ic] =
            __float2half_rn(win[(size_t)oc * 1728 + i]);
    }
}

// ---------------- main MMA kernel ----------------
// CTA: M=128 pixels (one (z,y) row), N=128 oc (half), 256 thr = 8 warps (4M x 2N).
// 27 K-stages = taps; A slab per (kz,ky) (9 slabs) reused across 3 kx via row shift.
// Stage K = 64 ic = 4 k16 chunks.
__global__ void __launch_bounds__(256, 2)
upsmpl_mma_kernel(const float* __restrict__ xin, const float* __restrict__ bin,
                  float* __restrict__ outp)
{
    extern __shared__ __half smh[];
    const int tid  = threadIdx.x;
    const int lane = tid & 31, wid = tid >> 5;
    const int g = lane >> 2, tig = lane & 3;
    const int wm = wid & 3, wn = wid >> 2;

    const int y  = blockIdx.x;          // 0..127
    const int z  = blockIdx.y;          // 0..16
    const int ocbase = blockIdx.z * 128;

    const uint32_t sA = smem_u32(smh);
    const uint32_t sB = sA + 3u * ABUF * 2u;

    // ldmatrix lane address pieces (byte units):
    // lanes 0-7: rows 0-7 +0B; 8-15: rows 8-15 +0B; 16-23: rows 0-7 +16B; 24-31: rows 8-15 +16B
    const int lrow  = ((lane >> 3) & 1) * 8 + (lane & 7);
    const int lcolB = (lane >> 4) * 16;
    const uint32_t aLaneOff = (uint32_t)((wm * 32 + lrow) * 144 + lcolB);
    const uint32_t bLaneOff = (uint32_t)((wn * 64 + lrow) * 144 + lcolB);

    auto loadA = [&](int s) {           // slab s = kz*3+ky  (0..8)
        const int kz = s / 3, ky = s % 3;
        const __half* src = g_xTh + ((size_t)(z + kz) * YP + (y + ky)) * XPD * ICN;
        const uint32_t dst = sA + (uint32_t)(s % 3) * ABUF * 2u;
        for (int i = tid; i < 1040; i += 256) {     // 130 rows x 8 x 16B
            int r = i >> 3, c = i & 7;
            cpa16(dst + (uint32_t)(r * 144 + c * 16),
                  (const char*)(src + (size_t)r * ICN) + c * 16);
        }
    };
    auto loadB = [&](int tap) {         // stage = tap
        const __half* src = g_Wth + ((size_t)tap * NOC + ocbase) * ICN;
        const uint32_t dst = sB + (uint32_t)(tap % 3) * BBUF * 2u;
        for (int i = tid; i < 1024; i += 256) {     // 128 rows x 8 x 16B
            int r = i >> 3, c = i & 7;
            cpa16(dst + (uint32_t)(r * 144 + c * 16),
                  (const char*)(src + (size_t)r * ICN) + c * 16);
        }
    };

    float d[2][8][4];
    #pragma unroll
    for (int mf = 0; mf < 2; ++mf)
        #pragma unroll
        for (int f = 0; f < 8; ++f)
            #pragma unroll
            for (int r = 0; r < 4; ++r) d[mf][f][r] = 0.f;

    loadA(0); loadB(0); CP_COMMIT();
    loadB(1); CP_COMMIT();              // stage 1 uses slab 0 (kx=1)

    for (int j = 0; j < 27; ++j) {
        CP_WAIT1();
        __syncthreads();   // publishes stage-j data; fences stage j-1 reads so
                           // the loads below may overwrite recycled buffers.

        const uint32_t Ab = sA + (uint32_t)((j / 3) % 3) * ABUF * 2u;
        const uint32_t Bb = sB + (uint32_t)(j % 3) * BBUF * 2u;
        const int kx = j - (j / 3) * 3;
        const uint32_t aBase = Ab + aLaneOff + (uint32_t)(kx * 144);
        const uint32_t bBase = Bb + bLaneOff;

        #pragma unroll
        for (int c = 0; c < 4; ++c) {   // k16 chunks: +32B each
            uint32_t a[2][4], b[8][2];
            #pragma unroll
            for (int mf = 0; mf < 2; ++mf)
                ldsm4(a[mf][0], a[mf][1], a[mf][2], a[mf][3],
                      aBase + (uint32_t)(mf * 16 * 144 + c * 32));
            #pragma unroll
            for (int f2 = 0; f2 < 4; ++f2)
                ldsm4(b[2 * f2][0], b[2 * f2 + 1][0], b[2 * f2][1], b[2 * f2 + 1][1],
                      bBase + (uint32_t)(f2 * 16 * 144 + c * 32));
            #pragma unroll
            for (int mf = 0; mf < 2; ++mf)
                #pragma unroll
                for (int f = 0; f < 8; ++f)
                    mma16(d[mf][f], a[mf], b[f]);
        }

        if (j + 2 < 27) {
            loadB(j + 2);
            if ((j + 2) % 3 == 0) loadA((j + 2) / 3);
        }
        CP_COMMIT();                     // one group per iteration (may be empty)
    }

    // ---------------- epilogue: bias + shuffle scatter + skip ----------------
    #pragma unroll
    for (int mf = 0; mf < 2; ++mf) {
        #pragma unroll
        for (int rh = 0; rh < 2; ++rh) {
            const int x = wm * 32 + mf * 16 + rh * 8 + g;
            if (z == 0) {
                #pragma unroll
                for (int f = 0; f < 4; ++f) {       // f>=4 -> oc&32 -> discarded
                    #pragma unroll
                    for (int par = 0; par < 2; ++par) {
                        const int oc = ocbase + wn * 64 + f * 8 + 2 * tig + par;
                        const int q = (oc >> 6) & 1, p = oc >> 7, nn = oc & 31;
                        const int sic = (p * 64 + q * 32 + nn) >> 1;
                        const float v = d[mf][f][rh * 2 + par] + bin[oc]
                                      + xin[(size_t)sic * 17 * 16384 + (size_t)y * 128 + x];
                        outp[((size_t)nn * 33 * 256 + (2 * y + p)) * 256 + 2 * x + q] = v;
                    }
                }
            } else {
                #pragma unroll
                for (int f = 0; f < 4; ++f) {
                    #pragma unroll
                    for (int par = 0; par < 2; ++par) {
                        const int oc0 = ocbase + wn * 64 + f * 8 + 2 * tig + par;
                        const int oc1 = oc0 + 32;   // q=1 partner
                        const float v0 = d[mf][f][rh * 2 + par] + bin[oc0]
                            + xin[((size_t)(oc0 >> 2) * 17 + z) * 16384 + (size_t)y * 128 + x];
                        const float v1 = d[mf][f + 4][rh * 2 + par] + bin[oc1]
                            + xin[((size_t)(oc1 >> 2) * 17 + z) * 16384 + (size_t)y * 128 + x];
                        const int nn = oc0 & 31, p = (oc0 >> 6) & 1, a = oc0 >> 7;
                        const size_t o = (((size_t)nn * 33 + (2 * z - 1 + a)) * 256
                                          + (2 * y + p)) * 256 + 2 * x;
                        *(float2*)(outp + o) = make_float2(v0, v1);
                    }
                }
            }
        }
    }
}

extern "C" void kernel_launch(void* const* d_in, const int* in_sizes, int n_in,
                              void* d_out, int out_size) {
    const float* x = (const float*)d_in[0];
    const float* W = (const float*)d_in[1];
    const float* b = (const float*)d_in[2];
    float* out = (float*)d_out;

    cudaFuncSetAttribute(upsmpl_mma_kernel,
                         cudaFuncAttributeMaxDynamicSharedMemorySize, SMEM_BYTES);

    size_t n8 = (size_t)ZP * YP * XPD * ICN / 8;
    zero_xT_kernel<<<(unsigned)((n8 + 255) / 256), 256>>>();
    prep_x_kernel<<<dim3(128, 17), 256>>>(x);
    prep_w_kernel<<<256, 256>>>(W);
    upsmpl_mma_kernel<<<dim3(128, 17, 2), 256, SMEM_BYTES>>>(x, b, out);
}